// round 1
// baseline (speedup 1.0000x reference)
#include <cuda_runtime.h>
#include <math.h>

#define N_ENT   100000
#define D       128
#define N_EDGES 1600000
#define BATCH   8192
#define EPS     1e-5f

// output layout: [loss(1)] [age_pred(8192*7)] [gender_pred(8192)] [occ_pred(8192*21)]
#define OFF_AGE  1
#define OFF_G    (1 + BATCH * 7)
#define OFF_OCC  (OFF_G + BATCH)

// ---------------- device scratch (static, no allocation) ----------------
__device__ __align__(16) float g_colsum[D];
__device__ __align__(16) float g_colsumsq[D];
__device__ __align__(16) float g_scale[D];
__device__ __align__(16) float g_shift[D];
__device__ int   g_flags[N_ENT];
__device__ int   g_counts[N_ENT];
__device__ int   g_cursor[N_ENT];
__device__ int   g_offsets[N_ENT];
__device__ int   g_ebuf[N_EDGES];
__device__ __align__(16) float g_hin[BATCH * D];
__device__ __align__(16) float g_u[BATCH * D];
__device__ float g_bce[BATCH];

// ---------------- kernels ----------------

__global__ void k_init() {
    int i = blockIdx.x * blockDim.x + threadIdx.x;
    int stride = gridDim.x * blockDim.x;
    for (int j = i; j < N_ENT; j += stride) {
        g_flags[j] = 0;
        g_counts[j] = 0;
        g_cursor[j] = 0;
    }
    if (i < D) {
        g_colsum[i] = 0.0f;
        g_colsumsq[i] = 0.0f;
    }
}

__global__ void k_mark(const int* __restrict__ nb) {
    int i = blockIdx.x * blockDim.x + threadIdx.x;
    if (i < BATCH) g_flags[nb[i]] = 1;
}

// column sums / sums of squares over E  (blockDim = 128, one column per thread)
__global__ void k_colstats(const float* __restrict__ E) {
    int j = threadIdx.x;
    int rows_per = (N_ENT + gridDim.x - 1) / gridDim.x;
    int r0 = blockIdx.x * rows_per;
    int r1 = r0 + rows_per;
    if (r1 > N_ENT) r1 = N_ENT;
    float s = 0.0f, s2 = 0.0f;
#pragma unroll 4
    for (int r = r0; r < r1; r++) {
        float v = E[(size_t)r * D + j];
        s += v;
        s2 += v * v;
    }
    atomicAdd(&g_colsum[j], s);
    atomicAdd(&g_colsumsq[j], s2);
}

__global__ void k_finalize(const float* __restrict__ gamma, const float* __restrict__ beta) {
    int j = threadIdx.x;
    const float invn = 1.0f / (float)N_ENT;
    float mean = g_colsum[j] * invn;
    float var = g_colsumsq[j] * invn - mean * mean;
    float sc = rsqrtf(var + EPS) * gamma[j];
    g_scale[j] = sc;
    g_shift[j] = beta[j] - mean * sc;
}

__global__ void k_count(const int* __restrict__ dst) {
    int stride = gridDim.x * blockDim.x;
    for (int e = blockIdx.x * blockDim.x + threadIdx.x; e < N_EDGES; e += stride) {
        int d = dst[e];
        if (g_flags[d]) atomicAdd(&g_counts[d], 1);
    }
}

// exclusive prefix sum of g_counts -> g_offsets, single block of 1024 threads
__global__ void k_scan() {
    __shared__ int s_part[1024];
    const int T = 1024;
    const int CH = (N_ENT + T - 1) / T;   // 98
    int t = threadIdx.x;
    int start = t * CH;
    int end = start + CH;
    if (end > N_ENT) end = N_ENT;
    int sum = 0;
    for (int i = start; i < end; i++) sum += g_counts[i];
    s_part[t] = sum;
    __syncthreads();
    for (int off = 1; off < T; off <<= 1) {
        int v = (t >= off) ? s_part[t - off] : 0;
        __syncthreads();
        s_part[t] += v;
        __syncthreads();
    }
    int run = (t == 0) ? 0 : s_part[t - 1];
    for (int i = start; i < end; i++) {
        g_offsets[i] = run;
        run += g_counts[i];
    }
}

__global__ void k_fill(const int* __restrict__ src, const int* __restrict__ dst) {
    int stride = gridDim.x * blockDim.x;
    for (int e = blockIdx.x * blockDim.x + threadIdx.x; e < N_EDGES; e += stride) {
        int d = dst[e];
        if (g_flags[d]) {
            int p = atomicAdd(&g_cursor[d], 1);
            g_ebuf[g_offsets[d] + p] = src[e];
        }
    }
}

// one warp per batch row: sum raw E rows of in-neighbors, apply affine + degree div
__global__ void k_gather(const float* __restrict__ E, const int* __restrict__ nb) {
    int warp = (blockIdx.x * blockDim.x + threadIdx.x) >> 5;
    int lane = threadIdx.x & 31;
    if (warp >= BATCH) return;
    int node = nb[warp];
    int deg = g_counts[node];
    int start = g_offsets[node];
    const float4* E4 = (const float4*)E;
    float4 acc = make_float4(0.f, 0.f, 0.f, 0.f);
    int i = 0;
    for (; i + 4 <= deg; i += 4) {
        int s0 = g_ebuf[start + i + 0];
        int s1 = g_ebuf[start + i + 1];
        int s2 = g_ebuf[start + i + 2];
        int s3 = g_ebuf[start + i + 3];
        float4 a = E4[(size_t)s0 * 32 + lane];
        float4 b = E4[(size_t)s1 * 32 + lane];
        float4 c = E4[(size_t)s2 * 32 + lane];
        float4 d = E4[(size_t)s3 * 32 + lane];
        acc.x += a.x + b.x + c.x + d.x;
        acc.y += a.y + b.y + c.y + d.y;
        acc.z += a.z + b.z + c.z + d.z;
        acc.w += a.w + b.w + c.w + d.w;
    }
    for (; i < deg; i++) {
        int s = g_ebuf[start + i];
        float4 a = E4[(size_t)s * 32 + lane];
        acc.x += a.x; acc.y += a.y; acc.z += a.z; acc.w += a.w;
    }
    float fdeg = (float)deg;
    float inv = 1.0f / fmaxf(fdeg, 1.0f);
    float4 sc = ((const float4*)g_scale)[lane];
    float4 sh = ((const float4*)g_shift)[lane];
    float4 o;
    o.x = (acc.x * sc.x + fdeg * sh.x) * inv;
    o.y = (acc.y * sc.y + fdeg * sh.y) * inv;
    o.z = (acc.z * sc.z + fdeg * sh.z) * inv;
    o.w = (acc.w * sc.w + fdeg * sh.w) * inv;
    ((float4*)g_hin)[(size_t)warp * 32 + lane] = o;
}

// u = relu(hin @ W_gnn + b_gnn): 32 rows per block, 128 threads (one output col each)
__global__ void k_gemm(const float* __restrict__ W, const float* __restrict__ b_gnn) {
    __shared__ float sA[32][D];
    int tid = threadIdx.x;
    int row0 = blockIdx.x * 32;
    for (int r = 0; r < 32; r++)
        sA[r][tid] = g_hin[(size_t)(row0 + r) * D + tid];
    __syncthreads();
    float acc[32];
#pragma unroll
    for (int r = 0; r < 32; r++) acc[r] = 0.0f;
    for (int k = 0; k < D; k += 4) {
        float w0 = W[(k + 0) * D + tid];
        float w1 = W[(k + 1) * D + tid];
        float w2 = W[(k + 2) * D + tid];
        float w3 = W[(k + 3) * D + tid];
#pragma unroll
        for (int r = 0; r < 32; r++) {
            float4 a = *(const float4*)&sA[r][k];
            acc[r] += a.x * w0 + a.y * w1 + a.z * w2 + a.w * w3;
        }
    }
    float bb = b_gnn[tid];
    for (int r = 0; r < 32; r++)
        g_u[(size_t)(row0 + r) * D + tid] = fmaxf(acc[r] + bb, 0.0f);
}

// one warp per batch row: gender/age/occ heads + per-row BCE term
__global__ void k_heads(const float* __restrict__ Wg, const float* __restrict__ bg,
                        const float* __restrict__ Wage, const float* __restrict__ bage,
                        const float* __restrict__ Wocc, const float* __restrict__ bocc,
                        const int* __restrict__ gender, float* __restrict__ out) {
    int warp = (blockIdx.x * blockDim.x + threadIdx.x) >> 5;
    int lane = threadIdx.x & 31;
    if (warp >= BATCH) return;
    float4 u = ((const float4*)g_u)[(size_t)warp * 32 + lane];
    int j0 = lane * 4;

    // gender head
    float4 wg = ((const float4*)Wg)[lane];
    float v = u.x * wg.x + u.y * wg.y + u.z * wg.z + u.w * wg.w;
#pragma unroll
    for (int off = 16; off; off >>= 1) v += __shfl_xor_sync(0xffffffffu, v, off);
    float x = v + bg[0];
    if (lane == 0) {
        out[OFF_G + warp] = x;
        float z = (float)gender[warp];
        g_bce[warp] = fmaxf(x, 0.0f) - x * z + log1pf(expf(-fabsf(x)));
    }

    // age head (7 cols)
#pragma unroll
    for (int c = 0; c < 7; c++) {
        float p = u.x * Wage[(j0 + 0) * 7 + c] + u.y * Wage[(j0 + 1) * 7 + c]
                + u.z * Wage[(j0 + 2) * 7 + c] + u.w * Wage[(j0 + 3) * 7 + c];
#pragma unroll
        for (int off = 16; off; off >>= 1) p += __shfl_xor_sync(0xffffffffu, p, off);
        if (lane == 0) out[OFF_AGE + (size_t)warp * 7 + c] = p + bage[c];
    }

    // occupation head (21 cols)
#pragma unroll
    for (int c = 0; c < 21; c++) {
        float p = u.x * Wocc[(j0 + 0) * 21 + c] + u.y * Wocc[(j0 + 1) * 21 + c]
                + u.z * Wocc[(j0 + 2) * 21 + c] + u.w * Wocc[(j0 + 3) * 21 + c];
#pragma unroll
        for (int off = 16; off; off >>= 1) p += __shfl_xor_sync(0xffffffffu, p, off);
        if (lane == 0) out[OFF_OCC + (size_t)warp * 21 + c] = p + bocc[c];
    }
}

// deterministic mean of g_bce -> out[0]
__global__ void k_loss(float* __restrict__ out) {
    __shared__ float s[1024];
    int t = threadIdx.x;
    float v = 0.0f;
    for (int i = t; i < BATCH; i += 1024) v += g_bce[i];
    s[t] = v;
    __syncthreads();
    for (int off = 512; off; off >>= 1) {
        if (t < off) s[t] += s[t + off];
        __syncthreads();
    }
    if (t == 0) out[0] = s[0] * (1.0f / (float)BATCH);
}

// ---------------- launch ----------------
extern "C" void kernel_launch(void* const* d_in, const int* in_sizes, int n_in,
                              void* d_out, int out_size) {
    const float* E      = (const float*)d_in[0];
    const float* gamma  = (const float*)d_in[1];
    const float* beta   = (const float*)d_in[2];
    const float* W_gnn  = (const float*)d_in[3];
    const float* b_gnn  = (const float*)d_in[4];
    const float* W_g    = (const float*)d_in[5];
    const float* b_g    = (const float*)d_in[6];
    const float* W_age  = (const float*)d_in[7];
    const float* b_age  = (const float*)d_in[8];
    const float* W_occ  = (const float*)d_in[9];
    const float* b_occ  = (const float*)d_in[10];
    const int*   src    = (const int*)d_in[11];
    const int*   dst    = (const int*)d_in[12];
    const int*   nb     = (const int*)d_in[13];
    const int*   gender = (const int*)d_in[14];
    float* out = (float*)d_out;

    k_init<<<256, 256>>>();
    k_mark<<<(BATCH + 255) / 256, 256>>>(nb);
    k_colstats<<<800, 128>>>(E);
    k_finalize<<<1, 128>>>(gamma, beta);
    k_count<<<2048, 256>>>(dst);
    k_scan<<<1, 1024>>>();
    k_fill<<<2048, 256>>>(src, dst);
    k_gather<<<BATCH / 8, 256>>>(E, nb);
    k_gemm<<<BATCH / 32, 128>>>(W_gnn, b_gnn);
    k_heads<<<BATCH / 8, 256>>>(W_g, b_g, W_age, b_age, W_occ, b_occ, gender, out);
    k_loss<<<1, 1024>>>(out);
}

// round 2
// speedup vs baseline: 1.8022x; 1.8022x over previous
#include <cuda_runtime.h>
#include <math.h>

#define N_ENT   100000
#define D       128
#define N_EDGES 1600000
#define BATCH   8192
#define EPS     1e-5f

#define NB 148          // persistent blocks (== min SM count, all co-resident)
#define NT 1024

// output layout: [loss(1)] [age(8192*7)] [gender(8192)] [occ(8192*21)]
#define OFF_AGE  1
#define OFF_G    (1 + BATCH * 7)
#define OFF_OCC  (OFF_G + BATCH)

// ---------------- persistent device state ----------------
__device__ __align__(16) float g_partsum[NB * D];
__device__ __align__(16) float g_partsq[NB * D];
__device__ __align__(16) float g_scale[D];
__device__ __align__(16) float g_shift[D];
__device__ int   g_slot[N_ENT];      // 0 = unflagged, else slot+1 (self-cleaned)
__device__ int   g_nslots;
__device__ int   g_cnt[BATCH];
__device__ int   g_cur[BATCH];
__device__ int   g_off[BATCH];
__device__ int   g_ebuf[N_EDGES];
__device__ __align__(16) float g_hin[BATCH * D];
__device__ __align__(16) float g_u[BATCH * D];
__device__ float g_bce[BATCH];
__device__ unsigned g_bar_cnt;
__device__ unsigned g_bar_gen;

// ---------------- software grid barrier ----------------
__device__ __forceinline__ void grid_barrier() {
    __threadfence();          // make this thread's writes device-visible
    __syncthreads();
    if (threadIdx.x == 0) {
        unsigned gen = g_bar_gen;          // read BEFORE arriving
        unsigned t = atomicAdd(&g_bar_cnt, 1);
        if (t == NB - 1) {
            g_bar_cnt = 0;
            __threadfence();
            atomicAdd(&g_bar_gen, 1);      // release
        } else {
            while (((volatile unsigned*)&g_bar_gen)[0] == gen) __nanosleep(64);
            __threadfence();               // acquire
        }
    }
    __syncthreads();
}

// ---------------- the one kernel ----------------
__global__ void __launch_bounds__(NT, 1)
gal_persistent(const float* __restrict__ E,
               const float* __restrict__ gamma, const float* __restrict__ beta,
               const float* __restrict__ W_gnn, const float* __restrict__ b_gnn,
               const float* __restrict__ Wg,    const float* __restrict__ bg,
               const float* __restrict__ Wage,  const float* __restrict__ bage,
               const float* __restrict__ Wocc,  const float* __restrict__ bocc,
               const int* __restrict__ src,     const int* __restrict__ dst,
               const int* __restrict__ nb,      const int* __restrict__ gender,
               float* __restrict__ out) {
    __shared__ __align__(16) char s_raw[32768];
    const int bid = blockIdx.x;
    const int tid = threadIdx.x;
    const int gid = bid * NT + tid;
    const int lane = tid & 31;
    const int widx = tid >> 5;                    // warp within block (0..31)
    const int gwarp = bid * 32 + widx;            // global warp id (0..4735)

    // ================= P0: mark/claim slots + column-stat partials =========
    if (gid < BATCH) {
        int node = nb[gid];
        int old = atomicCAS(&g_slot[node], 0, -1);
        if (old == 0) {
            int s = atomicAdd(&g_nslots, 1);
            g_slot[node] = s + 1;
        }
    }
    {
        // rows [r0, r1) for this block; 8 row-groups x 128 cols
        const int rows_per = (N_ENT + NB - 1) / NB;   // 676
        int r0 = bid * rows_per;
        int r1 = r0 + rows_per; if (r1 > N_ENT) r1 = N_ENT;
        int col = tid & 127;
        int grp = tid >> 7;                            // 0..7
        float s = 0.0f, s2 = 0.0f;
        for (int r = r0 + grp; r < r1; r += 8) {
            float v = E[(size_t)r * D + col];
            s += v; s2 += v * v;
        }
        float* sf = (float*)s_raw;                     // [1024] sum, [1024] sq
        sf[tid] = s;
        sf[NT + tid] = s2;
        __syncthreads();
        if (tid < 256) {
            int c = tid & 127;
            int which = tid >> 7;                      // 0: sum, 1: sq
            float acc = 0.0f;
            for (int g = 0; g < 8; g++) acc += sf[which * NT + g * 128 + c];
            if (which == 0) g_partsum[bid * D + c] = acc;
            else            g_partsq[bid * D + c] = acc;
        }
    }
    grid_barrier();

    // ================= P1: count edges into per-slot counters ==============
    for (int e = gid; e < N_EDGES; e += NB * NT) {
        int s = g_slot[dst[e]];
        if (s > 0) atomicAdd(&g_cnt[s - 1], 1);
    }
    grid_barrier();

    // ================= P2: block0 scan offsets | block1 finalize BN ========
    if (bid == 0) {
        int ns = g_nslots;                             // <= 8192
        int* si = (int*)s_raw;                         // [1024]
        int c0 = tid * 8;
        int sum = 0;
        for (int i = c0; i < c0 + 8 && i < ns; i++) sum += g_cnt[i];
        si[tid] = sum;
        __syncthreads();
        // Hillis-Steele inclusive scan over 1024 partials
        for (int offd = 1; offd < NT; offd <<= 1) {
            int v = (tid >= offd) ? si[tid - offd] : 0;
            __syncthreads();
            si[tid] += v;
            __syncthreads();
        }
        int run = (tid == 0) ? 0 : si[tid - 1];
        for (int i = c0; i < c0 + 8 && i < ns; i++) {
            g_off[i] = run;
            run += g_cnt[i];
        }
    } else if (bid == 1 && tid < D) {
        float s = 0.0f, s2 = 0.0f;
        for (int b = 0; b < NB; b++) {
            s  += g_partsum[b * D + tid];
            s2 += g_partsq[b * D + tid];
        }
        const float invn = 1.0f / (float)N_ENT;
        float mean = s * invn;
        float var = s2 * invn - mean * mean;
        float sc = rsqrtf(var + EPS) * gamma[tid];
        g_scale[tid] = sc;
        g_shift[tid] = beta[tid] - mean * sc;
    }
    grid_barrier();

    // ================= P3: fill CSR lists ==================================
    for (int e = gid; e < N_EDGES; e += NB * NT) {
        int d = dst[e];
        int s = g_slot[d];
        if (s > 0) {
            int p = atomicAdd(&g_cur[s - 1], 1);
            g_ebuf[g_off[s - 1] + p] = src[e];
        }
    }
    grid_barrier();

    // ================= P4: gather + affine (one warp per batch row) ========
    for (int row = gwarp; row < BATCH; row += NB * 32) {
        int node = nb[row];
        int s = g_slot[node] - 1;
        int deg = g_cnt[s];
        int start = g_off[s];
        const float4* E4 = (const float4*)E;
        float4 acc = make_float4(0.f, 0.f, 0.f, 0.f);
        int i = 0;
        for (; i + 4 <= deg; i += 4) {
            int s0 = g_ebuf[start + i + 0];
            int s1 = g_ebuf[start + i + 1];
            int s2 = g_ebuf[start + i + 2];
            int s3 = g_ebuf[start + i + 3];
            float4 a = E4[(size_t)s0 * 32 + lane];
            float4 b = E4[(size_t)s1 * 32 + lane];
            float4 c = E4[(size_t)s2 * 32 + lane];
            float4 d = E4[(size_t)s3 * 32 + lane];
            acc.x += a.x + b.x + c.x + d.x;
            acc.y += a.y + b.y + c.y + d.y;
            acc.z += a.z + b.z + c.z + d.z;
            acc.w += a.w + b.w + c.w + d.w;
        }
        for (; i < deg; i++) {
            int sv = g_ebuf[start + i];
            float4 a = E4[(size_t)sv * 32 + lane];
            acc.x += a.x; acc.y += a.y; acc.z += a.z; acc.w += a.w;
        }
        float fdeg = (float)deg;
        float inv = 1.0f / fmaxf(fdeg, 1.0f);
        float4 sc = ((const float4*)g_scale)[lane];
        float4 sh = ((const float4*)g_shift)[lane];
        float4 o;
        o.x = (acc.x * sc.x + fdeg * sh.x) * inv;
        o.y = (acc.y * sc.y + fdeg * sh.y) * inv;
        o.z = (acc.z * sc.z + fdeg * sh.z) * inv;
        o.w = (acc.w * sc.w + fdeg * sh.w) * inv;
        ((float4*)g_hin)[(size_t)row * 32 + lane] = o;
    }
    grid_barrier();

    // ================= P5: u = relu(hin @ W_gnn + b) ========================
    // 128 blocks, 64-row tile each; thread = (col 0..127, rowgroup 0..7)
    if (bid < BATCH / 64) {
        float* sA = (float*)s_raw;                     // [64][128]
        int row0 = bid * 64;
        const float4* hin4 = (const float4*)&g_hin[(size_t)row0 * D];
        float4* sA4 = (float4*)sA;
        for (int i = tid; i < 64 * 32; i += NT) sA4[i] = hin4[i];
        __syncthreads();
        int col = tid & 127;
        int grp = tid >> 7;                            // rows grp*8 .. grp*8+7
        float acc[8];
#pragma unroll
        for (int r = 0; r < 8; r++) acc[r] = 0.0f;
        for (int k = 0; k < D; k += 4) {
            float w0 = W_gnn[(k + 0) * D + col];
            float w1 = W_gnn[(k + 1) * D + col];
            float w2 = W_gnn[(k + 2) * D + col];
            float w3 = W_gnn[(k + 3) * D + col];
#pragma unroll
            for (int r = 0; r < 8; r++) {
                float4 a = *(const float4*)&sA[(grp * 8 + r) * D + k];
                acc[r] += a.x * w0 + a.y * w1 + a.z * w2 + a.w * w3;
            }
        }
        float bb = b_gnn[col];
#pragma unroll
        for (int r = 0; r < 8; r++)
            g_u[(size_t)(row0 + grp * 8 + r) * D + col] = fmaxf(acc[r] + bb, 0.0f);
    }
    grid_barrier();

    // ================= P6: heads (one warp per batch row) ==================
    for (int row = gwarp; row < BATCH; row += NB * 32) {
        float4 u = ((const float4*)g_u)[(size_t)row * 32 + lane];
        int j0 = lane * 4;

        float4 wg = ((const float4*)Wg)[lane];
        float v = u.x * wg.x + u.y * wg.y + u.z * wg.z + u.w * wg.w;
#pragma unroll
        for (int off = 16; off; off >>= 1) v += __shfl_xor_sync(0xffffffffu, v, off);
        float x = v + bg[0];
        if (lane == 0) {
            out[OFF_G + row] = x;
            float z = (float)gender[row];
            g_bce[row] = fmaxf(x, 0.0f) - x * z + log1pf(expf(-fabsf(x)));
        }

#pragma unroll
        for (int c = 0; c < 7; c++) {
            float p = u.x * Wage[(j0 + 0) * 7 + c] + u.y * Wage[(j0 + 1) * 7 + c]
                    + u.z * Wage[(j0 + 2) * 7 + c] + u.w * Wage[(j0 + 3) * 7 + c];
#pragma unroll
            for (int off = 16; off; off >>= 1) p += __shfl_xor_sync(0xffffffffu, p, off);
            if (lane == 0) out[OFF_AGE + (size_t)row * 7 + c] = p + bage[c];
        }

#pragma unroll
        for (int c = 0; c < 21; c++) {
            float p = u.x * Wocc[(j0 + 0) * 21 + c] + u.y * Wocc[(j0 + 1) * 21 + c]
                    + u.z * Wocc[(j0 + 2) * 21 + c] + u.w * Wocc[(j0 + 3) * 21 + c];
#pragma unroll
            for (int off = 16; off; off >>= 1) p += __shfl_xor_sync(0xffffffffu, p, off);
            if (lane == 0) out[OFF_OCC + (size_t)row * 21 + c] = p + bocc[c];
        }
    }
    grid_barrier();

    // ================= P7: block0 loss reduce | others clean state =========
    if (bid == 0) {
        float* sf = (float*)s_raw;
        float v = 0.0f;
        for (int i = tid; i < BATCH; i += NT) v += g_bce[i];
        sf[tid] = v;
        __syncthreads();
        for (int off = 512; off; off >>= 1) {
            if (tid < off) sf[tid] += sf[tid + off];
            __syncthreads();
        }
        if (tid == 0) out[0] = sf[0] * (1.0f / (float)BATCH);
    } else {
        // self-clean so the next graph replay sees pristine state
        int g2 = (bid - 1) * NT + tid;
        int stride = (NB - 1) * NT;
        for (int i = g2; i < BATCH; i += stride) {
            g_slot[nb[i]] = 0;   // clears every claimed node (dupes harmless)
            g_cnt[i] = 0;
            g_cur[i] = 0;
        }
        if (bid == 1 && tid == 0) g_nslots = 0;
    }
}

// ---------------- launch ----------------
extern "C" void kernel_launch(void* const* d_in, const int* in_sizes, int n_in,
                              void* d_out, int out_size) {
    const float* E      = (const float*)d_in[0];
    const float* gamma  = (const float*)d_in[1];
    const float* beta   = (const float*)d_in[2];
    const float* W_gnn  = (const float*)d_in[3];
    const float* b_gnn  = (const float*)d_in[4];
    const float* W_g    = (const float*)d_in[5];
    const float* b_g    = (const float*)d_in[6];
    const float* W_age  = (const float*)d_in[7];
    const float* b_age  = (const float*)d_in[8];
    const float* W_occ  = (const float*)d_in[9];
    const float* b_occ  = (const float*)d_in[10];
    const int*   src    = (const int*)d_in[11];
    const int*   dst    = (const int*)d_in[12];
    const int*   nb     = (const int*)d_in[13];
    const int*   gender = (const int*)d_in[14];
    float* out = (float*)d_out;

    gal_persistent<<<NB, NT>>>(E, gamma, beta, W_gnn, b_gnn, W_g, b_g,
                               W_age, b_age, W_occ, b_occ,
                               src, dst, nb, gender, out);
}